// round 1
// baseline (speedup 1.0000x reference)
#include <cuda_runtime.h>
#include <cstdint>

#define T_SEQ 32768
#define HID   512
#define CS    8        // cluster size per direction

// 64 MB scratch for xp = x @ Wx^T + b  (device global: allowed, no runtime alloc)
__device__ float g_xp[(size_t)T_SEQ * HID];

// ---------------------------------------------------------------------------
// Kernel 1: xp[m,n] = sum_k x[m,k] * Wx[n,k] + b[n]
// Classic 128x128x16 fp32 SIMT GEMM, both operands K-contiguous (NT layout).
// ---------------------------------------------------------------------------
#define BM 128
#define BN 128
#define BK 16

__global__ void __launch_bounds__(256) gemm_xp_kernel(
    const float* __restrict__ x, const float* __restrict__ Wx,
    const float* __restrict__ b)
{
    __shared__ float As[BK][BM + 4];
    __shared__ float Bs[BK][BN + 4];
    const int bm  = blockIdx.y * BM;
    const int bn  = blockIdx.x * BN;
    const int tid = threadIdx.x;
    const int tx  = tid & 15;   // 0..15 -> 8 output cols each
    const int ty  = tid >> 4;   // 0..15 -> 8 output rows each

    float acc[8][8];
#pragma unroll
    for (int i = 0; i < 8; i++)
#pragma unroll
        for (int j = 0; j < 8; j++) acc[i][j] = 0.f;

    for (int k0 = 0; k0 < HID; k0 += BK) {
#pragma unroll
        for (int i = 0; i < 2; i++) {
            int idx = tid * 2 + i;           // 0..511
            int r   = idx >> 2;              // 0..127
            int c4  = (idx & 3) * 4;         // 0,4,8,12
            float4 va = *(const float4*)&x [(size_t)(bm + r) * HID + k0 + c4];
            As[c4 + 0][r] = va.x; As[c4 + 1][r] = va.y;
            As[c4 + 2][r] = va.z; As[c4 + 3][r] = va.w;
            float4 vb = *(const float4*)&Wx[(size_t)(bn + r) * HID + k0 + c4];
            Bs[c4 + 0][r] = vb.x; Bs[c4 + 1][r] = vb.y;
            Bs[c4 + 2][r] = vb.z; Bs[c4 + 3][r] = vb.w;
        }
        __syncthreads();
#pragma unroll
        for (int k = 0; k < BK; k++) {
            float a[8], bb[8];
#pragma unroll
            for (int i = 0; i < 8; i++) a[i]  = As[k][ty * 8 + i];
#pragma unroll
            for (int j = 0; j < 8; j++) bb[j] = Bs[k][tx * 8 + j];
#pragma unroll
            for (int i = 0; i < 8; i++)
#pragma unroll
                for (int j = 0; j < 8; j++)
                    acc[i][j] = fmaf(a[i], bb[j], acc[i][j]);
        }
        __syncthreads();
    }

#pragma unroll
    for (int i = 0; i < 8; i++) {
        int m = bm + ty * 8 + i;
#pragma unroll
        for (int j = 0; j < 8; j += 4) {
            int n = bn + tx * 8 + j;
            float4 v;
            v.x = acc[i][j + 0] + b[n + 0];
            v.y = acc[i][j + 1] + b[n + 1];
            v.z = acc[i][j + 2] + b[n + 2];
            v.w = acc[i][j + 3] + b[n + 3];
            *(float4*)&g_xp[(size_t)m * HID + n] = v;
        }
    }
}

// ---------------------------------------------------------------------------
// Kernel 2: the two recurrent scans. 2 clusters x 8 CTAs x 512 threads.
// CTA rank rk owns output rows [rk*64, rk*64+64). Each thread owns
// Wh[row, sub*64 .. sub*64+63] in registers (packed f32x2). h lives in a
// padded, double-buffered smem replica in every CTA; new chunks are pushed
// to all peers via st.shared::cluster, ordered by barrier.cluster.
// ---------------------------------------------------------------------------
__device__ __forceinline__ uint32_t smem_u32(const void* p) {
    uint32_t a;
    asm("{ .reg .u64 t; cvta.to.shared.u64 t, %1; cvt.u32.u64 %0, t; }"
        : "=r"(a) : "l"(p));
    return a;
}

#define HPAD (CS * 68)   // 512 cols padded: word = col + 4*(col/64)

__global__ void __launch_bounds__(512, 1) __cluster_dims__(CS, 1, 1)
scan_kernel(const float* __restrict__ Wh, float* __restrict__ out)
{
    __shared__ float hs[2][HPAD];

    const int tid       = threadIdx.x;
    const int dir       = blockIdx.x / CS;   // 0 = forward, 1 = reverse
    const int rk        = blockIdx.x % CS;   // cluster rank
    const int row_local = tid >> 3;          // 0..63
    const int sub       = tid & 7;           // 0..7 (column chunk)
    const int row       = rk * 64 + row_local;

    // ---- load weights into registers, packed as f32x2 pairs ----
    unsigned long long w2[32];
    {
        const ulonglong2* wp =
            (const ulonglong2*)&Wh[(size_t)row * HID + sub * 64];
#pragma unroll
        for (int i = 0; i < 16; i++) {
            ulonglong2 v = wp[i];
            w2[2 * i]     = v.x;
            w2[2 * i + 1] = v.y;
        }
    }

    // ---- zero both h buffers (h0 = 0) ----
    for (int i = tid; i < 2 * HPAD; i += 512) ((float*)hs)[i] = 0.f;

    // ---- peer smem base addresses ----
    uint32_t base_local = smem_u32(&hs[0][0]);
    uint32_t peer[CS];
#pragma unroll
    for (int p = 0; p < CS; p++) {
        asm("mapa.shared::cluster.u32 %0, %1, %2;"
            : "=r"(peer[p]) : "r"(base_local), "r"(p));
    }

    asm volatile("barrier.cluster.arrive.aligned;" ::: "memory");
    asm volatile("barrier.cluster.wait.aligned;"   ::: "memory");

    float* out_h = out + 512 + (size_t)dir * T_SEQ * HID;

    // ---- xp software pipeline (depth 2) ----
    float xp0, xp1;
    {
        size_t i0 = (size_t)(dir ? (T_SEQ - 1) : 0) * HID + row;
        size_t i1 = (size_t)(dir ? (T_SEQ - 2) : 1) * HID + row;
        xp0 = g_xp[i0];
        xp1 = g_xp[i1];
    }

    int p = 0;
    for (int t = 0; t < T_SEQ; t++) {
        // prefetch xp for step t+2 (hidden behind this step's work)
        float xpn = 0.f;
        if (t + 2 < T_SEQ) {
            size_t ii = (size_t)(dir ? (T_SEQ - 3 - t) : (t + 2)) * HID + row;
            xpn = __ldg(&g_xp[ii]);
        }

        // ---- partial matvec: 64 cols, packed f32x2 FMA ----
        const float* hp = &hs[p][68 * sub];
        unsigned long long accA = 0ull, accB = 0ull;
#pragma unroll
        for (int k = 0; k < 16; k++) {
            ulonglong2 hv = *(const ulonglong2*)(hp + 4 * k);
            asm("fma.rn.f32x2 %0, %1, %2, %3;"
                : "=l"(accA) : "l"(w2[2 * k]),     "l"(hv.x), "l"(accA));
            asm("fma.rn.f32x2 %0, %1, %2, %3;"
                : "=l"(accB) : "l"(w2[2 * k + 1]), "l"(hv.y), "l"(accB));
        }
        uint32_t alo, ahi, blo, bhi;
        asm("mov.b64 {%0,%1}, %2;" : "=r"(alo), "=r"(ahi) : "l"(accA));
        asm("mov.b64 {%0,%1}, %2;" : "=r"(blo), "=r"(bhi) : "l"(accB));
        float a = (__uint_as_float(alo) + __uint_as_float(ahi))
                + (__uint_as_float(blo) + __uint_as_float(bhi));

        // reduce across the 8 sub-threads of this row (lanes aligned to 8)
        a += __shfl_xor_sync(0xffffffffu, a, 1);
        a += __shfl_xor_sync(0xffffffffu, a, 2);
        a += __shfl_xor_sync(0xffffffffu, a, 4);

        float h = tanhf(a + xp0);

        if (sub == 0) {
            out_h[(size_t)t * HID + row] = h;
            // push my new h value into every CTA's next buffer
            uint32_t off =
                (uint32_t)(((p ^ 1) * HPAD + rk * 68 + row_local) * 4);
#pragma unroll
            for (int pr = 0; pr < CS; pr++) {
                asm volatile("st.shared::cluster.f32 [%0], %1;"
                             :: "r"(peer[pr] + off), "f"(h) : "memory");
            }
        }

        xp0 = xp1;
        xp1 = xpn;

        asm volatile("barrier.cluster.arrive.aligned;" ::: "memory");
        asm volatile("barrier.cluster.wait.aligned;"   ::: "memory");
        p ^= 1;
    }
}

// ---------------------------------------------------------------------------
// Kernel 3: y = Wout @ concat(h_fwd[-1], h_rev[-1]) + bout
// ---------------------------------------------------------------------------
__global__ void __launch_bounds__(256) readout_kernel(
    const float* __restrict__ Wout, const float* __restrict__ bout,
    float* __restrict__ out)
{
    const int j = blockIdx.x;   // 512 blocks: one output row each
    const float* hf = out + 512 + (size_t)(T_SEQ - 1) * HID;
    const float* hr = out + 512 + (size_t)T_SEQ * HID + (size_t)(T_SEQ - 1) * HID;
    const float* wr = Wout + (size_t)j * (2 * HID);

    float s = 0.f;
    for (int i = threadIdx.x; i < HID; i += 256) s = fmaf(wr[i],       hf[i], s);
    for (int i = threadIdx.x; i < HID; i += 256) s = fmaf(wr[HID + i], hr[i], s);

#pragma unroll
    for (int o = 16; o > 0; o >>= 1) s += __shfl_xor_sync(0xffffffffu, s, o);

    __shared__ float red[8];
    if ((threadIdx.x & 31) == 0) red[threadIdx.x >> 5] = s;
    __syncthreads();
    if (threadIdx.x == 0) {
        float tot = 0.f;
#pragma unroll
        for (int i = 0; i < 8; i++) tot += red[i];
        out[j] = tot + bout[j];
    }
}

// ---------------------------------------------------------------------------
extern "C" void kernel_launch(void* const* d_in, const int* in_sizes, int n_in,
                              void* d_out, int out_size)
{
    const float* x    = (const float*)d_in[0];
    const float* Wx   = (const float*)d_in[1];
    const float* Wh   = (const float*)d_in[2];
    const float* b    = (const float*)d_in[3];
    const float* Wout = (const float*)d_in[4];
    const float* bout = (const float*)d_in[5];
    float* out = (float*)d_out;

    dim3 ggrid(HID / BN, T_SEQ / BM);           // (4, 256)
    gemm_xp_kernel<<<ggrid, 256>>>(x, Wx, b);

    scan_kernel<<<2 * CS, 512>>>(Wh, out);      // 2 clusters of 8 CTAs

    readout_kernel<<<HID, 256>>>(Wout, bout, out);
}

// round 2
// speedup vs baseline: 1.2952x; 1.2952x over previous
#include <cuda_runtime.h>
#include <cstdint>

#define T_SEQ 32768
#define HID   512
#define CS    8        // cluster size per direction

// 64 MB scratch for xp = x @ Wx^T + b  (device global: allowed, no runtime alloc)
__device__ float g_xp[(size_t)T_SEQ * HID];

// ---------------------------------------------------------------------------
// Kernel 1: xp[m,n] = sum_k x[m,k] * Wx[n,k] + b[n]   (unchanged from R1)
// ---------------------------------------------------------------------------
#define BM 128
#define BN 128
#define BK 16

__global__ void __launch_bounds__(256) gemm_xp_kernel(
    const float* __restrict__ x, const float* __restrict__ Wx,
    const float* __restrict__ b)
{
    __shared__ float As[BK][BM + 4];
    __shared__ float Bs[BK][BN + 4];
    const int bm  = blockIdx.y * BM;
    const int bn  = blockIdx.x * BN;
    const int tid = threadIdx.x;
    const int tx  = tid & 15;
    const int ty  = tid >> 4;

    float acc[8][8];
#pragma unroll
    for (int i = 0; i < 8; i++)
#pragma unroll
        for (int j = 0; j < 8; j++) acc[i][j] = 0.f;

    for (int k0 = 0; k0 < HID; k0 += BK) {
#pragma unroll
        for (int i = 0; i < 2; i++) {
            int idx = tid * 2 + i;
            int r   = idx >> 2;
            int c4  = (idx & 3) * 4;
            float4 va = *(const float4*)&x [(size_t)(bm + r) * HID + k0 + c4];
            As[c4 + 0][r] = va.x; As[c4 + 1][r] = va.y;
            As[c4 + 2][r] = va.z; As[c4 + 3][r] = va.w;
            float4 vb = *(const float4*)&Wx[(size_t)(bn + r) * HID + k0 + c4];
            Bs[c4 + 0][r] = vb.x; Bs[c4 + 1][r] = vb.y;
            Bs[c4 + 2][r] = vb.z; Bs[c4 + 3][r] = vb.w;
        }
        __syncthreads();
#pragma unroll
        for (int k = 0; k < BK; k++) {
            float a[8], bb[8];
#pragma unroll
            for (int i = 0; i < 8; i++) a[i]  = As[k][ty * 8 + i];
#pragma unroll
            for (int j = 0; j < 8; j++) bb[j] = Bs[k][tx * 8 + j];
#pragma unroll
            for (int i = 0; i < 8; i++)
#pragma unroll
                for (int j = 0; j < 8; j++)
                    acc[i][j] = fmaf(a[i], bb[j], acc[i][j]);
        }
        __syncthreads();
    }

#pragma unroll
    for (int i = 0; i < 8; i++) {
        int m = bm + ty * 8 + i;
#pragma unroll
        for (int j = 0; j < 8; j += 4) {
            int n = bn + tx * 8 + j;
            float4 v;
            v.x = acc[i][j + 0] + b[n + 0];
            v.y = acc[i][j + 1] + b[n + 1];
            v.z = acc[i][j + 2] + b[n + 2];
            v.w = acc[i][j + 3] + b[n + 3];
            *(float4*)&g_xp[(size_t)m * HID + n] = v;
        }
    }
}

// ---------------------------------------------------------------------------
// Kernel 2: recurrent scans. 2 clusters x 8 CTAs x 512 threads.
// Sync per step: local STS + __syncthreads + 7x cp.async.bulk (256B) to peers,
// each signaling the peer's ping-pong mbarrier via complete_tx::bytes.
// ---------------------------------------------------------------------------
__device__ __forceinline__ uint32_t smem_u32(const void* p) {
    uint32_t a;
    asm("{ .reg .u64 t; cvta.to.shared.u64 t, %1; cvt.u32.u64 %0, t; }"
        : "=r"(a) : "l"(p));
    return a;
}

#define MBAR_INIT(addr, cnt) \
    asm volatile("mbarrier.init.shared.b64 [%0], %1;" :: "r"(addr), "r"(cnt) : "memory")

#define MBAR_EXPECT_TX(addr, tx) \
    asm volatile("mbarrier.arrive.expect_tx.shared.b64 _, [%0], %1;" \
                 :: "r"(addr), "r"(tx) : "memory")

#define MBAR_WAIT(addr, ph) do {                                               \
    uint32_t _done;                                                            \
    asm volatile("{\n\t.reg .pred p;\n\t"                                      \
        "mbarrier.try_wait.parity.acquire.cta.shared::cta.b64 p, [%1], %2;\n\t"\
        "selp.b32 %0, 1, 0, p;\n\t}"                                           \
        : "=r"(_done) : "r"(addr), "r"(ph) : "memory");                        \
    if (!_done) {                                                              \
        asm volatile("{\n\t.reg .pred P1;\n\t"                                 \
            "WL_%=:\n\t"                                                       \
            "mbarrier.try_wait.parity.acquire.cta.shared::cta.b64 P1, [%0], %1, 0x989680;\n\t" \
            "@P1 bra.uni WD_%=;\n\t"                                           \
            "bra.uni WL_%=;\n\t"                                               \
            "WD_%=:\n\t}"                                                      \
            :: "r"(addr), "r"(ph) : "memory");                                 \
    }                                                                          \
} while (0)

#define HPAD 544   // 8 chunks * 68 words: word = col + 4*(col/64), conflict-free

__global__ void __launch_bounds__(512, 1) __cluster_dims__(CS, 1, 1)
scan_kernel(const float* __restrict__ Wh, float* __restrict__ out)
{
    __shared__ alignas(16) float hs[2][HPAD];
    __shared__ alignas(8) unsigned long long mbar[2];

    const int tid       = threadIdx.x;
    const int dir       = blockIdx.x / CS;   // 0 = forward, 1 = reverse
    const int rk        = blockIdx.x % CS;   // cluster rank
    const int row_local = tid >> 3;          // 0..63
    const int sub       = tid & 7;           // 0..7 (column chunk)
    const int row       = rk * 64 + row_local;

    // ---- weights into registers as f32x2 pairs: 4 independent chains ----
    unsigned long long w2[32];
    {
        const ulonglong2* wp =
            (const ulonglong2*)&Wh[(size_t)row * HID + sub * 64];
#pragma unroll
        for (int i = 0; i < 16; i++) {
            ulonglong2 v = wp[i];
            w2[2 * i]     = v.x;
            w2[2 * i + 1] = v.y;
        }
    }

    // ---- zero both h buffers (h0 = 0) ----
    for (int i = tid; i < 2 * HPAD; i += 512) ((float*)hs)[i] = 0.f;

    const uint32_t buf0 = smem_u32(&hs[0][0]);
    const uint32_t buf1 = smem_u32(&hs[1][0]);
    const uint32_t mb   = smem_u32(&mbar[0]);

    if (tid == 0) {
        MBAR_INIT(mb,     1u);
        MBAR_INIT(mb + 8, 1u);
    }
    __syncthreads();
    // all CTAs: buffers zeroed + mbars initialized before any remote bulk
    asm volatile("barrier.cluster.arrive.aligned;" ::: "memory");
    asm volatile("barrier.cluster.wait.aligned;"   ::: "memory");

    float* out_h = out + 512 + (size_t)dir * T_SEQ * HID;

    // ---- xp software pipeline (depth 2) ----
    float xp0, xp1;
    {
        size_t i0 = (size_t)(dir ? (T_SEQ - 1) : 0) * HID + row;
        size_t i1 = (size_t)(dir ? (T_SEQ - 2) : 1) * HID + row;
        xp0 = g_xp[i0];
        xp1 = g_xp[i1];
    }

    int ph0 = 0, ph1 = 0;

    for (int t = 0; t < T_SEQ; t++) {
        float xpn = 0.f;
        if (t + 2 < T_SEQ) {
            size_t ii = (size_t)(dir ? (T_SEQ - 3 - t) : (t + 2)) * HID + row;
            xpn = __ldg(&g_xp[ii]);
        }

        const int cur = t & 1;
        if (t > 0) {
            if (cur) { MBAR_WAIT(mb + 8, ph1); ph1 ^= 1; }
            else     { MBAR_WAIT(mb,     ph0); ph0 ^= 1; }
        }

        // ---- partial matvec: 64 cols, 4 independent f32x2 FMA chains ----
        const float* hp = &hs[cur][68 * sub];
        unsigned long long a0 = 0ull, a1 = 0ull, a2 = 0ull, a3 = 0ull;
#pragma unroll
        for (int k = 0; k < 8; k++) {
            ulonglong2 hA = *(const ulonglong2*)(hp + 8 * k);
            ulonglong2 hB = *(const ulonglong2*)(hp + 8 * k + 4);
            asm("fma.rn.f32x2 %0, %1, %2, %3;"
                : "=l"(a0) : "l"(w2[4 * k + 0]), "l"(hA.x), "l"(a0));
            asm("fma.rn.f32x2 %0, %1, %2, %3;"
                : "=l"(a1) : "l"(w2[4 * k + 1]), "l"(hA.y), "l"(a1));
            asm("fma.rn.f32x2 %0, %1, %2, %3;"
                : "=l"(a2) : "l"(w2[4 * k + 2]), "l"(hB.x), "l"(a2));
            asm("fma.rn.f32x2 %0, %1, %2, %3;"
                : "=l"(a3) : "l"(w2[4 * k + 3]), "l"(hB.y), "l"(a3));
        }
        uint32_t l0, h0, l1, h1, l2, h2, l3, h3;
        asm("mov.b64 {%0,%1}, %2;" : "=r"(l0), "=r"(h0) : "l"(a0));
        asm("mov.b64 {%0,%1}, %2;" : "=r"(l1), "=r"(h1) : "l"(a1));
        asm("mov.b64 {%0,%1}, %2;" : "=r"(l2), "=r"(h2) : "l"(a2));
        asm("mov.b64 {%0,%1}, %2;" : "=r"(l3), "=r"(h3) : "l"(a3));
        float s = ((__uint_as_float(l0) + __uint_as_float(h0))
                 + (__uint_as_float(l1) + __uint_as_float(h1)))
                + ((__uint_as_float(l2) + __uint_as_float(h2))
                 + (__uint_as_float(l3) + __uint_as_float(h3)));

        // reduce across the 8 sub-threads of this row
        s += __shfl_xor_sync(0xffffffffu, s, 1);
        s += __shfl_xor_sync(0xffffffffu, s, 2);
        s += __shfl_xor_sync(0xffffffffu, s, 4);

        float z = s + xp0;
        // fast accurate tanh: h = 1 - 2/(exp(2z)+1), via ex2/rcp MUFU
        float e, r;
        asm("ex2.approx.f32 %0, %1;" : "=f"(e) : "f"(z * 2.885390082f));
        asm("rcp.approx.f32 %0, %1;" : "=f"(r) : "f"(e + 1.0f));
        float h = fmaf(-2.0f, r, 1.0f);

        if (sub == 0) {
            out_h[(size_t)t * HID + row] = h;
            hs[cur ^ 1][68 * rk + row_local] = h;   // local copy of my chunk
        }
        __syncthreads();   // my chunk visible CTA-wide (and to async proxy)

        if (t + 1 < T_SEQ && tid == 0) {
            const uint32_t j    = cur ^ 1;
            const uint32_t lmb  = mb + 8u * j;
            const uint32_t lbuf = j ? buf1 : buf0;
            const uint32_t src  = lbuf + (uint32_t)rk * 272u;
            MBAR_EXPECT_TX(lmb, 1792u);             // 7 peers x 256B
            asm volatile("fence.proxy.async.shared::cta;" ::: "memory");
#pragma unroll
            for (int pr = 0; pr < CS; pr++) {
                if (pr == rk) continue;
                uint32_t dst, rmb;
                asm("mapa.shared::cluster.u32 %0, %1, %2;"
                    : "=r"(dst) : "r"(src), "r"(pr));
                asm("mapa.shared::cluster.u32 %0, %1, %2;"
                    : "=r"(rmb) : "r"(lmb), "r"(pr));
                asm volatile(
                    "cp.async.bulk.shared::cluster.shared::cta.mbarrier::complete_tx::bytes "
                    "[%0], [%1], %2, [%3];"
                    :: "r"(dst), "r"(src), "r"(256u), "r"(rmb) : "memory");
            }
        }

        xp0 = xp1;
        xp1 = xpn;
    }
}

// ---------------------------------------------------------------------------
// Kernel 3: y = Wout @ concat(h_fwd[-1], h_rev[-1]) + bout   (unchanged)
// ---------------------------------------------------------------------------
__global__ void __launch_bounds__(256) readout_kernel(
    const float* __restrict__ Wout, const float* __restrict__ bout,
    float* __restrict__ out)
{
    const int j = blockIdx.x;
    const float* hf = out + 512 + (size_t)(T_SEQ - 1) * HID;
    const float* hr = out + 512 + (size_t)T_SEQ * HID + (size_t)(T_SEQ - 1) * HID;
    const float* wr = Wout + (size_t)j * (2 * HID);

    float s = 0.f;
    for (int i = threadIdx.x; i < HID; i += 256) s = fmaf(wr[i],       hf[i], s);
    for (int i = threadIdx.x; i < HID; i += 256) s = fmaf(wr[HID + i], hr[i], s);

#pragma unroll
    for (int o = 16; o > 0; o >>= 1) s += __shfl_xor_sync(0xffffffffu, s, o);

    __shared__ float red[8];
    if ((threadIdx.x & 31) == 0) red[threadIdx.x >> 5] = s;
    __syncthreads();
    if (threadIdx.x == 0) {
        float tot = 0.f;
#pragma unroll
        for (int i = 0; i < 8; i++) tot += red[i];
        out[j] = tot + bout[j];
    }
}

// ---------------------------------------------------------------------------
extern "C" void kernel_launch(void* const* d_in, const int* in_sizes, int n_in,
                              void* d_out, int out_size)
{
    const float* x    = (const float*)d_in[0];
    const float* Wx   = (const float*)d_in[1];
    const float* Wh   = (const float*)d_in[2];
    const float* b    = (const float*)d_in[3];
    const float* Wout = (const float*)d_in[4];
    const float* bout = (const float*)d_in[5];
    float* out = (float*)d_out;

    dim3 ggrid(HID / BN, T_SEQ / BM);           // (4, 256)
    gemm_xp_kernel<<<ggrid, 256>>>(x, Wx, b);

    scan_kernel<<<2 * CS, 512>>>(Wh, out);      // 2 clusters of 8 CTAs

    readout_kernel<<<HID, 256>>>(Wout, bout, out);
}

// round 3
// speedup vs baseline: 1.4658x; 1.1317x over previous
#include <cuda_runtime.h>
#include <cstdint>

#define T_SEQ 32768
#define HID   512
#define CS    8        // cluster size per direction

// 64 MB scratch for xp = x @ Wx^T + b  (device global: allowed, no runtime alloc)
__device__ float g_xp[(size_t)T_SEQ * HID];

// ---------------------------------------------------------------------------
// Kernel 1: xp[m,n] = sum_k x[m,k] * Wx[n,k] + b[n]   (unchanged)
// ---------------------------------------------------------------------------
#define BM 128
#define BN 128
#define BK 16

__global__ void __launch_bounds__(256) gemm_xp_kernel(
    const float* __restrict__ x, const float* __restrict__ Wx,
    const float* __restrict__ b)
{
    __shared__ float As[BK][BM + 4];
    __shared__ float Bs[BK][BN + 4];
    const int bm  = blockIdx.y * BM;
    const int bn  = blockIdx.x * BN;
    const int tid = threadIdx.x;
    const int tx  = tid & 15;
    const int ty  = tid >> 4;

    float acc[8][8];
#pragma unroll
    for (int i = 0; i < 8; i++)
#pragma unroll
        for (int j = 0; j < 8; j++) acc[i][j] = 0.f;

    for (int k0 = 0; k0 < HID; k0 += BK) {
#pragma unroll
        for (int i = 0; i < 2; i++) {
            int idx = tid * 2 + i;
            int r   = idx >> 2;
            int c4  = (idx & 3) * 4;
            float4 va = *(const float4*)&x [(size_t)(bm + r) * HID + k0 + c4];
            As[c4 + 0][r] = va.x; As[c4 + 1][r] = va.y;
            As[c4 + 2][r] = va.z; As[c4 + 3][r] = va.w;
            float4 vb = *(const float4*)&Wx[(size_t)(bn + r) * HID + k0 + c4];
            Bs[c4 + 0][r] = vb.x; Bs[c4 + 1][r] = vb.y;
            Bs[c4 + 2][r] = vb.z; Bs[c4 + 3][r] = vb.w;
        }
        __syncthreads();
#pragma unroll
        for (int k = 0; k < BK; k++) {
            float a[8], bb[8];
#pragma unroll
            for (int i = 0; i < 8; i++) a[i]  = As[k][ty * 8 + i];
#pragma unroll
            for (int j = 0; j < 8; j++) bb[j] = Bs[k][tx * 8 + j];
#pragma unroll
            for (int i = 0; i < 8; i++)
#pragma unroll
                for (int j = 0; j < 8; j++)
                    acc[i][j] = fmaf(a[i], bb[j], acc[i][j]);
        }
        __syncthreads();
    }

#pragma unroll
    for (int i = 0; i < 8; i++) {
        int m = bm + ty * 8 + i;
#pragma unroll
        for (int j = 0; j < 8; j += 4) {
            int n = bn + tx * 8 + j;
            float4 v;
            v.x = acc[i][j + 0] + b[n + 0];
            v.y = acc[i][j + 1] + b[n + 1];
            v.z = acc[i][j + 2] + b[n + 2];
            v.w = acc[i][j + 3] + b[n + 3];
            *(float4*)&g_xp[(size_t)m * HID + n] = v;
        }
    }
}

// ---------------------------------------------------------------------------
// Kernel 2: recurrent scans. 2 clusters x 8 CTAs x 512 threads.
// Publish path: each sub==0 thread fires 8x st.async (4B each) straight to
// every rank's next-phase buffer, signaling the receiver's ping-pong mbarrier
// via complete_tx::bytes. No syncthreads / bulk engine / proxy fence in loop.
// ---------------------------------------------------------------------------
__device__ __forceinline__ uint32_t smem_u32(const void* p) {
    uint32_t a;
    asm("{ .reg .u64 t; cvta.to.shared.u64 t, %1; cvt.u32.u64 %0, t; }"
        : "=r"(a) : "l"(p));
    return a;
}

#define MBAR_INIT(addr, cnt) \
    asm volatile("mbarrier.init.shared.b64 [%0], %1;" :: "r"(addr), "r"(cnt) : "memory")

// arrive (count 1) + add expected transaction bytes for the current phase
#define MBAR_ARRIVE_EXPECT_TX(addr, tx) \
    asm volatile("mbarrier.arrive.expect_tx.shared.b64 _, [%0], %1;" \
                 :: "r"(addr), "r"(tx) : "memory")

#define MBAR_WAIT(addr, ph) do {                                               \
    uint32_t _done;                                                            \
    asm volatile("{\n\t.reg .pred p;\n\t"                                      \
        "mbarrier.try_wait.parity.acquire.cta.shared::cta.b64 p, [%1], %2;\n\t"\
        "selp.b32 %0, 1, 0, p;\n\t}"                                           \
        : "=r"(_done) : "r"(addr), "r"(ph) : "memory");                        \
    if (!_done) {                                                              \
        asm volatile("{\n\t.reg .pred P1;\n\t"                                 \
            "WL_%=:\n\t"                                                       \
            "mbarrier.try_wait.parity.acquire.cta.shared::cta.b64 P1, [%0], %1, 0x989680;\n\t" \
            "@P1 bra.uni WD_%=;\n\t"                                           \
            "bra.uni WL_%=;\n\t"                                               \
            "WD_%=:\n\t}"                                                      \
            :: "r"(addr), "r"(ph) : "memory");                                 \
    }                                                                          \
} while (0)

#define HPAD 544   // 8 chunks * 68 words: word = col + 4*(col/64), conflict-free

__global__ void __launch_bounds__(512, 1) __cluster_dims__(CS, 1, 1)
scan_kernel(const float* __restrict__ Wh, float* __restrict__ out)
{
    __shared__ alignas(16) float hs[2][HPAD];
    __shared__ alignas(8) unsigned long long mbar[2];

    const int tid       = threadIdx.x;
    const int dir       = blockIdx.x / CS;   // 0 = forward, 1 = reverse
    const int rk        = blockIdx.x % CS;   // cluster rank
    const int row_local = tid >> 3;          // 0..63
    const int sub       = tid & 7;           // 0..7 (column chunk)
    const int row       = rk * 64 + row_local;

    // ---- weights into registers as f32x2 pairs: 4 independent chains ----
    unsigned long long w2[32];
    {
        const ulonglong2* wp =
            (const ulonglong2*)&Wh[(size_t)row * HID + sub * 64];
#pragma unroll
        for (int i = 0; i < 16; i++) {
            ulonglong2 v = wp[i];
            w2[2 * i]     = v.x;
            w2[2 * i + 1] = v.y;
        }
    }

    // ---- zero both h buffers (h0 = 0) ----
    for (int i = tid; i < 2 * HPAD; i += 512) ((float*)hs)[i] = 0.f;

    const uint32_t buf0 = smem_u32(&hs[0][0]);
    const uint32_t mb   = smem_u32(&mbar[0]);
    const uint32_t mbrel = mb - buf0;        // mbar offset relative to hs base

    // DSMEM addressing is linear in local offset -> one mapa per rank serves
    // both buffers and both mbarriers.
    uint32_t rank_base[CS];
#pragma unroll
    for (int r = 0; r < CS; r++) {
        asm("mapa.shared::cluster.u32 %0, %1, %2;"
            : "=r"(rank_base[r]) : "r"(buf0), "r"(r));
    }

    if (tid == 0) {
        MBAR_INIT(mb,     1u);
        MBAR_INIT(mb + 8, 1u);
        // pre-arm both phases' arrivals + tx expectations
        MBAR_ARRIVE_EXPECT_TX(mb,     2048u);
        MBAR_ARRIVE_EXPECT_TX(mb + 8, 2048u);
    }
    __syncthreads();
    // all CTAs: buffers zeroed + mbars armed before any remote st.async
    asm volatile("barrier.cluster.arrive.aligned;" ::: "memory");
    asm volatile("barrier.cluster.wait.aligned;"   ::: "memory");

    float* out_h = out + 512 + (size_t)dir * T_SEQ * HID;

    // destination offsets (relative to hs base) for my h value, per buffer
    const uint32_t doff0 = (uint32_t)(68 * rk + row_local) * 4u;
    const uint32_t doff1 = doff0 + (uint32_t)HPAD * 4u;

    // ---- xp software pipeline (depth 2) ----
    float xp0, xp1;
    {
        size_t i0 = (size_t)(dir ? (T_SEQ - 1) : 0) * HID + row;
        size_t i1 = (size_t)(dir ? (T_SEQ - 2) : 1) * HID + row;
        xp0 = g_xp[i0];
        xp1 = g_xp[i1];
    }

    int ph0 = 0, ph1 = 0;

    for (int t = 0; t < T_SEQ; t++) {
        float xpn = 0.f;
        if (t + 2 < T_SEQ) {
            size_t ii = (size_t)(dir ? (T_SEQ - 3 - t) : (t + 2)) * HID + row;
            xpn = __ldg(&g_xp[ii]);
        }

        const int cur = t & 1;
        if (t > 0) {
            if (cur) {
                MBAR_WAIT(mb + 8, ph1); ph1 ^= 1;
                // re-arm this mbar for its next phase (t+2 data). Early peer
                // tx are absorbed: mbarrier tx-count may go transiently
                // negative; phase completes only after this arrive.
                if (tid == 0 && t + 2 < T_SEQ)
                    MBAR_ARRIVE_EXPECT_TX(mb + 8, 2048u);
            } else {
                MBAR_WAIT(mb, ph0); ph0 ^= 1;
                if (tid == 0 && t + 2 < T_SEQ)
                    MBAR_ARRIVE_EXPECT_TX(mb, 2048u);
            }
        }

        // ---- partial matvec: 64 cols, 4 independent f32x2 FMA chains ----
        const float* hp = &hs[cur][68 * sub];
        unsigned long long a0 = 0ull, a1 = 0ull, a2 = 0ull, a3 = 0ull;
#pragma unroll
        for (int k = 0; k < 8; k++) {
            ulonglong2 hA = *(const ulonglong2*)(hp + 8 * k);
            ulonglong2 hB = *(const ulonglong2*)(hp + 8 * k + 4);
            asm("fma.rn.f32x2 %0, %1, %2, %3;"
                : "=l"(a0) : "l"(w2[4 * k + 0]), "l"(hA.x), "l"(a0));
            asm("fma.rn.f32x2 %0, %1, %2, %3;"
                : "=l"(a1) : "l"(w2[4 * k + 1]), "l"(hA.y), "l"(a1));
            asm("fma.rn.f32x2 %0, %1, %2, %3;"
                : "=l"(a2) : "l"(w2[4 * k + 2]), "l"(hB.x), "l"(a2));
            asm("fma.rn.f32x2 %0, %1, %2, %3;"
                : "=l"(a3) : "l"(w2[4 * k + 3]), "l"(hB.y), "l"(a3));
        }
        uint32_t l0, h0, l1, h1, l2, h2, l3, h3;
        asm("mov.b64 {%0,%1}, %2;" : "=r"(l0), "=r"(h0) : "l"(a0));
        asm("mov.b64 {%0,%1}, %2;" : "=r"(l1), "=r"(h1) : "l"(a1));
        asm("mov.b64 {%0,%1}, %2;" : "=r"(l2), "=r"(h2) : "l"(a2));
        asm("mov.b64 {%0,%1}, %2;" : "=r"(l3), "=r"(h3) : "l"(a3));
        float s = ((__uint_as_float(l0) + __uint_as_float(h0))
                 + (__uint_as_float(l1) + __uint_as_float(h1)))
                + ((__uint_as_float(l2) + __uint_as_float(h2))
                 + (__uint_as_float(l3) + __uint_as_float(h3)));

        // reduce across the 8 sub-threads of this row
        s += __shfl_xor_sync(0xffffffffu, s, 1);
        s += __shfl_xor_sync(0xffffffffu, s, 2);
        s += __shfl_xor_sync(0xffffffffu, s, 4);

        float z = s + xp0;
        // fast accurate tanh: h = 1 - 2/(exp(2z)+1), via ex2/rcp MUFU
        float e, r;
        asm("ex2.approx.f32 %0, %1;" : "=f"(e) : "f"(z * 2.885390082f));
        asm("rcp.approx.f32 %0, %1;" : "=f"(r) : "f"(e + 1.0f));
        float h = fmaf(-2.0f, r, 1.0f);

        if (sub == 0) {
            if (t + 1 < T_SEQ) {
                // publish h to every rank's next-phase buffer (incl. self)
                const uint32_t doff = cur ? doff0 : doff1;   // dest buf = cur^1
                const uint32_t moff = mbrel + (cur ? 0u : 8u);
#pragma unroll
                for (int pr = 0; pr < CS; pr++) {
                    asm volatile(
                        "st.async.weak.shared::cluster.mbarrier::complete_tx::bytes.f32 "
                        "[%0], %1, [%2];"
                        :: "r"(rank_base[pr] + doff), "f"(h),
                           "r"(rank_base[pr] + moff) : "memory");
                }
            }
            out_h[(size_t)t * HID + row] = h;
        }

        xp0 = xp1;
        xp1 = xpn;
    }
}

// ---------------------------------------------------------------------------
// Kernel 3: y = Wout @ concat(h_fwd[-1], h_rev[-1]) + bout   (unchanged)
// ---------------------------------------------------------------------------
__global__ void __launch_bounds__(256) readout_kernel(
    const float* __restrict__ Wout, const float* __restrict__ bout,
    float* __restrict__ out)
{
    const int j = blockIdx.x;
    const float* hf = out + 512 + (size_t)(T_SEQ - 1) * HID;
    const float* hr = out + 512 + (size_t)T_SEQ * HID + (size_t)(T_SEQ - 1) * HID;
    const float* wr = Wout + (size_t)j * (2 * HID);

    float s = 0.f;
    for (int i = threadIdx.x; i < HID; i += 256) s = fmaf(wr[i],       hf[i], s);
    for (int i = threadIdx.x; i < HID; i += 256) s = fmaf(wr[HID + i], hr[i], s);

#pragma unroll
    for (int o = 16; o > 0; o >>= 1) s += __shfl_xor_sync(0xffffffffu, s, o);

    __shared__ float red[8];
    if ((threadIdx.x & 31) == 0) red[threadIdx.x >> 5] = s;
    __syncthreads();
    if (threadIdx.x == 0) {
        float tot = 0.f;
#pragma unroll
        for (int i = 0; i < 8; i++) tot += red[i];
        out[j] = tot + bout[j];
    }
}

// ---------------------------------------------------------------------------
extern "C" void kernel_launch(void* const* d_in, const int* in_sizes, int n_in,
                              void* d_out, int out_size)
{
    const float* x    = (const float*)d_in[0];
    const float* Wx   = (const float*)d_in[1];
    const float* Wh   = (const float*)d_in[2];
    const float* b    = (const float*)d_in[3];
    const float* Wout = (const float*)d_in[4];
    const float* bout = (const float*)d_in[5];
    float* out = (float*)d_out;

    dim3 ggrid(HID / BN, T_SEQ / BM);           // (4, 256)
    gemm_xp_kernel<<<ggrid, 256>>>(x, Wx, b);

    scan_kernel<<<2 * CS, 512>>>(Wh, out);      // 2 clusters of 8 CTAs

    readout_kernel<<<HID, 256>>>(Wout, bout, out);
}